// round 1
// baseline (speedup 1.0000x reference)
#include <cuda_runtime.h>
#include <cuda_bf16.h>
#include <cstdint>

// ---------------------------------------------------------------------------
// HiddenInteractionTensor: V0 = (pt * s1) @ U0^T, V1 = (pt * s0) @ U1^T
// Rewritten as: V0 = pt @ (U0 * s1)^T,  V1 = pt @ (U1 * s0)^T
// s0 = colsum(U0), s1 = colsum(U1), K = 32.
// Output layout: [V0 (P x N0) row-major][V1 (P x N1) row-major]
// ---------------------------------------------------------------------------

#define R_DIM 32
#define BM 128
#define BN 64
#define APAD 4                // As row stride = 36 floats (16B aligned, bank-friendly)

__device__ float g_s[2][R_DIM];   // scratch: g_s[0]=colsum(U0), g_s[1]=colsum(U1)

// ---- packed f32x2 helpers (FFMA2 path, sm_100+) ----
__device__ __forceinline__ unsigned long long pack2(float lo, float hi) {
    unsigned long long r;
    asm("mov.b64 %0, {%1,%2};" : "=l"(r) : "f"(lo), "f"(hi));
    return r;
}
__device__ __forceinline__ void fma2(unsigned long long& d, unsigned long long a,
                                     unsigned long long b) {
    asm("fma.rn.f32x2 %0, %1, %2, %3;" : "=l"(d) : "l"(a), "l"(b), "l"(d));
}
__device__ __forceinline__ void unpack2(unsigned long long v, float& lo, float& hi) {
    asm("mov.b64 {%0,%1}, %2;" : "=f"(lo), "=f"(hi) : "l"(v));
}

// ---------------------------------------------------------------------------
// Column sums of the two factor matrices. blockIdx.x selects U0 / U1.
// Deterministic fixed-tree reduction (no float atomics).
// ---------------------------------------------------------------------------
__global__ void colsum_kernel(const float* __restrict__ U0, int n0,
                              const float* __restrict__ U1, int n1) {
    const float* U = (blockIdx.x == 0) ? U0 : U1;
    const int n    = (blockIdx.x == 0) ? n0 : n1;

    __shared__ float part[8][R_DIM];
    const int col = threadIdx.x & (R_DIM - 1);
    const int grp = threadIdx.x >> 5;          // 0..7 (256 threads)

    float acc = 0.0f;
    for (int r = grp; r < n; r += 8)
        acc += U[(size_t)r * R_DIM + col];
    part[grp][col] = acc;
    __syncthreads();

    if (threadIdx.x < R_DIM) {
        float s = 0.0f;
        #pragma unroll
        for (int g = 0; g < 8; ++g) s += part[g][col];
        g_s[blockIdx.x][threadIdx.x] = s;
    }
}

// ---------------------------------------------------------------------------
// Tiled GEMM: C[P,N] = A[P,32] @ (B[N,32] * s)^T
// BM=128 x BN=64 tile, 256 threads, each thread 8 (m) x 4 (n) outputs held as
// 16 packed f32x2 accumulators (pairs along n). K=32 fully unrolled.
// ---------------------------------------------------------------------------
__global__ __launch_bounds__(256)
void skinny_gemm_kernel(const float* __restrict__ A,
                        const float* __restrict__ B,
                        float* __restrict__ C,
                        int P, int N, int s_idx) {
    __shared__ float As[BM][R_DIM + APAD];   // [m][k], 16B-aligned rows
    __shared__ float Bs[R_DIM][BN];          // [k][n], scale fused on fill

    const int tid = threadIdx.x;
    const int m0  = blockIdx.y * BM;
    const int n0  = blockIdx.x * BN;

    // ---- load A tile: 128 rows x 8 float4 quads, 4 vectors per thread ----
    #pragma unroll
    for (int i = 0; i < 4; ++i) {
        int idx = i * 256 + tid;
        int r = idx >> 3, q = idx & 7;
        int row = m0 + r;
        float4 v = make_float4(0.f, 0.f, 0.f, 0.f);
        if (row < P) v = *(const float4*)(A + (size_t)row * R_DIM + q * 4);
        *(float4*)&As[r][q * 4] = v;         // conflict-free STS.128
    }

    // ---- load B tile scaled by s: 64 rows x 8 quads, 2 vectors/thread ----
    #pragma unroll
    for (int i = 0; i < 2; ++i) {
        int idx = i * 256 + tid;
        int r = idx >> 3, q = idx & 7;
        int n = n0 + r;
        float4 v = make_float4(0.f, 0.f, 0.f, 0.f);
        if (n < N) v = *(const float4*)(B + (size_t)n * R_DIM + q * 4);
        const float* s = g_s[s_idx];
        Bs[q * 4 + 0][r] = v.x * s[q * 4 + 0];
        Bs[q * 4 + 1][r] = v.y * s[q * 4 + 1];
        Bs[q * 4 + 2][r] = v.z * s[q * 4 + 2];
        Bs[q * 4 + 3][r] = v.w * s[q * 4 + 3];
    }
    __syncthreads();

    const int tx = tid & 15;   // n direction: 16 x 4 = 64
    const int ty = tid >> 4;   // m direction: 16 x 8 = 128

    unsigned long long acc[8][2];
    #pragma unroll
    for (int i = 0; i < 8; ++i) { acc[i][0] = 0ull; acc[i][1] = 0ull; }

    // ---- mainloop: K=32 as 8 quads of 4 ----
    #pragma unroll
    for (int k0 = 0; k0 < 8; ++k0) {
        // B rows for this k-quad (LDS.128, pairs along n are free packs)
        unsigned long long bp[4][2];
        #pragma unroll
        for (int kk = 0; kk < 4; ++kk) {
            float4 b = *(const float4*)&Bs[k0 * 4 + kk][tx * 4];
            bp[kk][0] = pack2(b.x, b.y);
            bp[kk][1] = pack2(b.z, b.w);
        }
        #pragma unroll
        for (int i = 0; i < 8; ++i) {
            float4 a = *(const float4*)&As[ty * 8 + i][k0 * 4];  // LDS.128 along k
            unsigned long long a0 = pack2(a.x, a.x);
            unsigned long long a1 = pack2(a.y, a.y);
            unsigned long long a2 = pack2(a.z, a.z);
            unsigned long long a3 = pack2(a.w, a.w);
            fma2(acc[i][0], a0, bp[0][0]); fma2(acc[i][1], a0, bp[0][1]);
            fma2(acc[i][0], a1, bp[1][0]); fma2(acc[i][1], a1, bp[1][1]);
            fma2(acc[i][0], a2, bp[2][0]); fma2(acc[i][1], a2, bp[2][1]);
            fma2(acc[i][0], a3, bp[3][0]); fma2(acc[i][1], a3, bp[3][1]);
        }
    }

    // ---- epilogue: 8 rows x float4 ----
    const int ncol = n0 + tx * 4;
    if (ncol < N) {                       // N % 4 == 0 -> whole vec valid or not
        #pragma unroll
        for (int i = 0; i < 8; ++i) {
            int row = m0 + ty * 8 + i;
            if (row < P) {
                float4 o;
                unpack2(acc[i][0], o.x, o.y);
                unpack2(acc[i][1], o.z, o.w);
                *(float4*)(C + (size_t)row * N + ncol) = o;
            }
        }
    }
}

// ---------------------------------------------------------------------------
extern "C" void kernel_launch(void* const* d_in, const int* in_sizes, int n_in,
                              void* d_out, int out_size) {
    const float* pt = (const float*)d_in[0];   // [P, 32]
    const float* U0 = (const float*)d_in[1];   // [N0, 32]
    const float* U1 = (const float*)d_in[2];   // [N1, 32]
    float* out = (float*)d_out;

    const int P  = in_sizes[0] / R_DIM;
    const int N0 = in_sizes[1] / R_DIM;
    const int N1 = in_sizes[2] / R_DIM;

    colsum_kernel<<<2, 256>>>(U0, N0, U1, N1);

    dim3 grid0((N0 + BN - 1) / BN, (P + BM - 1) / BM);
    skinny_gemm_kernel<<<grid0, 256>>>(pt, U0, out, P, N0, /*s1*/ 1);

    dim3 grid1((N1 + BN - 1) / BN, (P + BM - 1) / BM);
    skinny_gemm_kernel<<<grid1, 256>>>(pt, U1, out + (size_t)P * N0, P, N1, /*s0*/ 0);
}